// round 1
// baseline (speedup 1.0000x reference)
#include <cuda_runtime.h>
#include <cuda_bf16.h>
#include <math.h>

// ---------------------------------------------------------------------------
// Problem constants: B=8, N=1024, k=8
//  stage0: xyz(3) -> 64 -> 256   (BN over 8192 rows each)
//  stageA: group(256) -> 512 -> 512, max over k  (BN over 65536 rows)
//  stageB: group(512) -> 1024 -> 1024, max over k
//  output: (8, 1024ch, 1024pts) f32
// ---------------------------------------------------------------------------
#define NPTS 8192            // B*N
#define EPSV 1e-5f

// scratch (device globals; allocation-free)
__device__ float d_h1[NPTS * 64];
__device__ float d_h2[NPTS * 256];
__device__ int   d_knn[NPTS * 8];
__device__ float d_G[NPTS * 1024];
__device__ float d_C[NPTS * 1024];
__device__ float d_ymax[NPTS * 1024];
__device__ float d_ymin[NPTS * 1024];
__device__ float d_lA[NPTS * 512];
__device__ float d_sum[6 * 1024];
__device__ float d_sq[6 * 1024];
__device__ float d_scale[6 * 1024];
__device__ float d_shift[6 * 1024];

// ---------------------------------------------------------------------------
__global__ void k_zero(float* a, int n) {
    int i = blockIdx.x * 256 + threadIdx.x;
    if (i < n) a[i] = 0.f;
}

// ---------------------------------------------------------------------------
// kNN: per batch (1024 pts, 3-dim), 8 smallest d2 = sq[n]+sq[m]-2*dot.
// Stable tie-break (lower index wins) matches jax.lax.top_k.
__global__ void k_knn(const float* __restrict__ xyz) {
    __shared__ float sx[1024], sy[1024], sz[1024], sq[1024];
    int b = blockIdx.x >> 2;
    const float* base = xyz + b * 1024 * 3;
    for (int i = threadIdx.x; i < 1024; i += 256) {
        float x = base[i * 3], y = base[i * 3 + 1], z = base[i * 3 + 2];
        sx[i] = x; sy[i] = y; sz[i] = z;
        sq[i] = x * x + y * y + z * z;
    }
    __syncthreads();
    int n = (blockIdx.x & 3) * 256 + threadIdx.x;
    float px = sx[n], py = sy[n], pz = sz[n], pq = sq[n];
    float bd[8]; int bi[8];
#pragma unroll
    for (int j = 0; j < 8; j++) { bd[j] = 3.4e38f; bi[j] = -1; }
    for (int m = 0; m < 1024; m++) {
        float d2 = pq + sq[m] - 2.f * (px * sx[m] + py * sy[m] + pz * sz[m]);
        if (d2 < bd[7]) {
            float nd = d2; int ni = m;
#pragma unroll
            for (int t = 0; t < 8; t++) {
                if (nd < bd[t]) {
                    float td = bd[t]; int ti = bi[t];
                    bd[t] = nd; bi[t] = ni;
                    nd = td; ni = ti;
                }
            }
        }
    }
#pragma unroll
    for (int j = 0; j < 8; j++) d_knn[(b * 1024 + n) * 8 + j] = bi[j];
}

// ---------------------------------------------------------------------------
// Generic fp32 GEMM: Cout[M,N] = A[M,K] @ Weff[N,K]^T
//   Weff[o,d] = W[o*ldw + woff + d]  (minus W[o*ldw + d] if diffm)
// Optional per-column sum/sumsq accumulation (for BN stats).
// BM=64, BN=64, BK=16, 256 threads, 4x4 micro-tile.
__global__ __launch_bounds__(256) void k_gemm(
    const float* __restrict__ A, int lda,
    const float* __restrict__ W, int ldw, int woff, int diffm,
    float* __restrict__ Cout, int M, int N, int K,
    float* sum, float* sq)
{
    __shared__ float As[16][64];
    __shared__ float Ws[16][64];
    int tid = threadIdx.x;
    int mt = blockIdx.y * 64, nt = blockIdx.x * 64;
    int lr = tid >> 2;           // 0..63
    int lk = (tid & 3) * 4;      // 0,4,8,12
    int tx = tid & 15, ty = tid >> 4;
    float acc[4][4];
#pragma unroll
    for (int i = 0; i < 4; i++)
#pragma unroll
        for (int j = 0; j < 4; j++) acc[i][j] = 0.f;

    for (int kb = 0; kb < K; kb += 16) {
#pragma unroll
        for (int j = 0; j < 4; j++) {
            int kk = kb + lk + j;
            As[lk + j][lr] = (kk < K) ? A[(mt + lr) * lda + kk] : 0.f;
        }
#pragma unroll
        for (int j = 0; j < 4; j++) {
            int kk = kb + lk + j;
            float w = 0.f;
            if (kk < K) {
                w = W[(nt + lr) * ldw + woff + kk];
                if (diffm) w -= W[(nt + lr) * ldw + kk];
            }
            Ws[lk + j][lr] = w;
        }
        __syncthreads();
#pragma unroll
        for (int kk = 0; kk < 16; kk++) {
            float4 a = *(const float4*)&As[kk][ty * 4];
            float4 w = *(const float4*)&Ws[kk][tx * 4];
            float av[4] = {a.x, a.y, a.z, a.w};
            float wv[4] = {w.x, w.y, w.z, w.w};
#pragma unroll
            for (int i = 0; i < 4; i++)
#pragma unroll
                for (int j = 0; j < 4; j++)
                    acc[i][j] = fmaf(av[i], wv[j], acc[i][j]);
        }
        __syncthreads();
    }
    // write out
#pragma unroll
    for (int i = 0; i < 4; i++) {
        float4 v = make_float4(acc[i][0], acc[i][1], acc[i][2], acc[i][3]);
        *(float4*)&Cout[(mt + ty * 4 + i) * N + nt + tx * 4] = v;
    }
    if (sum) {
        float* red = &As[0][0];
        float ps[4], pq[4];
#pragma unroll
        for (int j = 0; j < 4; j++) {
            ps[j] = 0.f; pq[j] = 0.f;
#pragma unroll
            for (int i = 0; i < 4; i++) {
                ps[j] += acc[i][j];
                pq[j] += acc[i][j] * acc[i][j];
            }
        }
#pragma unroll
        for (int j = 0; j < 4; j++) red[ty * 64 + tx * 4 + j] = ps[j];
        __syncthreads();
        if (tid < 64) {
            float s = 0.f;
#pragma unroll
            for (int t = 0; t < 16; t++) s += red[t * 64 + tid];
            atomicAdd(&sum[nt + tid], s);
        }
        __syncthreads();
#pragma unroll
        for (int j = 0; j < 4; j++) red[ty * 64 + tx * 4 + j] = pq[j];
        __syncthreads();
        if (tid < 64) {
            float s = 0.f;
#pragma unroll
            for (int t = 0; t < 16; t++) s += red[t * 64 + tid];
            atomicAdd(&sq[nt + tid], s);
        }
    }
}

// ---------------------------------------------------------------------------
// Layer-1 preactivation stats over gathered G[idx]+C (never materialized).
// grid: (D/128, NPTS/8), block 128 (one channel per thread).
template <int D>
__global__ void k_stats1(float* sum1, float* sq1) {
    __shared__ int sidx[64];
    int d = blockIdx.x * 128 + threadIdx.x;
    int gbase = blockIdx.y * 8;
    if (threadIdx.x < 64) {
        int gi = threadIdx.x >> 3, kk = threadIdx.x & 7;
        int g = gbase + gi;
        sidx[threadIdx.x] = ((g >> 10) << 10) + d_knn[g * 8 + kk];
    }
    __syncthreads();
    float s = 0.f, ss = 0.f;
#pragma unroll
    for (int gi = 0; gi < 8; gi++) {
        int g = gbase + gi;
        float c = d_C[g * D + d];
#pragma unroll
        for (int kk = 0; kk < 8; kk++) {
            float x = d_G[sidx[gi * 8 + kk] * D + d] + c;
            s += x; ss += x * x;
        }
    }
    atomicAdd(&sum1[d], s);
    atomicAdd(&sq1[d], ss);
}

// ---------------------------------------------------------------------------
__global__ void k_finalize(const float* sum, const float* sq,
                           const float* g, const float* b,
                           float* scale, float* shift, int nch, float invcnt) {
    int c = blockIdx.x * 256 + threadIdx.x;
    if (c >= nch) return;
    float m = sum[c] * invcnt;
    float v = sq[c] * invcnt - m * m;
    float s = rsqrtf(v + EPSV) * g[c];
    scale[c] = s;
    shift[c] = b[c] - m * s;
}

__global__ void k_apply(float* x, const float* scale, const float* shift,
                        int total, int cmask) {
    int i = blockIdx.x * 256 + threadIdx.x;
    if (i >= total) return;
    int c = i & cmask;
    x[i] = fmaxf(fmaf(x[i], scale[c], shift[c]), 0.f);
}

__global__ void k_apply_sel(const float* ymax, const float* ymin,
                            const float* scale, const float* shift,
                            float* out, int total, int cmask) {
    int i = blockIdx.x * 256 + threadIdx.x;
    if (i >= total) return;
    int c = i & cmask;
    float s = scale[c];
    float v = (s >= 0.f) ? ymax[i] : ymin[i];
    out[i] = fmaxf(fmaf(v, s, shift[c]), 0.f);
}

// ---------------------------------------------------------------------------
// Fused layer-2: rows are (group g, k) with A generated on the fly:
//   Arow[d] = relu(fma(G[idx]+C, scale1[d], shift1[d]))
// y = A @ W2^T; epilogue: channel sum/sumsq (atomics) + per-(g,col) max/min.
// Tile: 64 rows (8 groups x k=8) x 128 cols, BK=16, 256 threads, micro 8x4
// (each thread owns all 8 k of one group -> max over k stays in registers).
template <int D>
__global__ __launch_bounds__(256) void k_layer2(
    const float* __restrict__ W2,
    const float* __restrict__ scale1, const float* __restrict__ shift1,
    float* sum2, float* sq2)
{
    __shared__ float As[16][64];
    __shared__ float Ws[16][128];
    __shared__ int spidx[64];
    int tid = threadIdx.x;
    int gbase = blockIdx.y * 8;
    int ot = blockIdx.x * 128;
    if (tid < 64) {
        int gi = tid >> 3, kk = tid & 7;
        int g = gbase + gi;
        spidx[tid] = ((g >> 10) << 10) + d_knn[g * 8 + kk];
    }
    __syncthreads();
    int ct = tid & 31, rg = tid >> 5;        // compute map: 32 col-threads x 8 groups
    int lr = tid >> 2, ld4 = (tid & 3) * 4;  // A load: row lr, 4 d's
    int lo = tid >> 1, lk8 = (tid & 1) * 8;  // W load: out-ch lo, 8 d's
    float acc[8][4];
#pragma unroll
    for (int r = 0; r < 8; r++)
#pragma unroll
        for (int j = 0; j < 4; j++) acc[r][j] = 0.f;

    int myp = spidx[lr];
    int myc = gbase + (lr >> 3);

    for (int kb = 0; kb < D; kb += 16) {
        {   // weights
            const float* wrow = W2 + (ot + lo) * D + kb + lk8;
            float4 w0 = *(const float4*)wrow;
            float4 w1 = *(const float4*)(wrow + 4);
            Ws[lk8 + 0][lo] = w0.x; Ws[lk8 + 1][lo] = w0.y;
            Ws[lk8 + 2][lo] = w0.z; Ws[lk8 + 3][lo] = w0.w;
            Ws[lk8 + 4][lo] = w1.x; Ws[lk8 + 5][lo] = w1.y;
            Ws[lk8 + 6][lo] = w1.z; Ws[lk8 + 7][lo] = w1.w;
        }
        {   // A generated on the fly (gather + BN + ReLU)
            float4 gv = *(const float4*)&d_G[myp * D + kb + ld4];
            float4 cv = *(const float4*)&d_C[myc * D + kb + ld4];
            float4 sc = *(const float4*)&scale1[kb + ld4];
            float4 sh = *(const float4*)&shift1[kb + ld4];
            As[ld4 + 0][lr] = fmaxf(fmaf(gv.x + cv.x, sc.x, sh.x), 0.f);
            As[ld4 + 1][lr] = fmaxf(fmaf(gv.y + cv.y, sc.y, sh.y), 0.f);
            As[ld4 + 2][lr] = fmaxf(fmaf(gv.z + cv.z, sc.z, sh.z), 0.f);
            As[ld4 + 3][lr] = fmaxf(fmaf(gv.w + cv.w, sc.w, sh.w), 0.f);
        }
        __syncthreads();
#pragma unroll
        for (int kk = 0; kk < 16; kk++) {
            float4 a0 = *(const float4*)&As[kk][rg * 8];
            float4 a1 = *(const float4*)&As[kk][rg * 8 + 4];
            float4 w  = *(const float4*)&Ws[kk][ct * 4];
            float av[8] = {a0.x, a0.y, a0.z, a0.w, a1.x, a1.y, a1.z, a1.w};
            float wv[4] = {w.x, w.y, w.z, w.w};
#pragma unroll
            for (int r = 0; r < 8; r++)
#pragma unroll
                for (int j = 0; j < 4; j++)
                    acc[r][j] = fmaf(av[r], wv[j], acc[r][j]);
        }
        __syncthreads();
    }
    // epilogue
    float cs[4], css[4], cmx[4], cmn[4];
#pragma unroll
    for (int j = 0; j < 4; j++) {
        cs[j] = 0.f; css[j] = 0.f; cmx[j] = -3.4e38f; cmn[j] = 3.4e38f;
    }
#pragma unroll
    for (int r = 0; r < 8; r++)
#pragma unroll
        for (int j = 0; j < 4; j++) {
            float v = acc[r][j];
            cs[j] += v; css[j] += v * v;
            cmx[j] = fmaxf(cmx[j], v);
            cmn[j] = fminf(cmn[j], v);
        }
    int g = gbase + rg;
    *(float4*)&d_ymax[g * D + ot + ct * 4] = make_float4(cmx[0], cmx[1], cmx[2], cmx[3]);
    *(float4*)&d_ymin[g * D + ot + ct * 4] = make_float4(cmn[0], cmn[1], cmn[2], cmn[3]);

    float* red = &Ws[0][0];
#pragma unroll
    for (int j = 0; j < 4; j++) red[rg * 128 + ct * 4 + j] = cs[j];
    __syncthreads();
    if (tid < 128) {
        float s = 0.f;
#pragma unroll
        for (int r = 0; r < 8; r++) s += red[r * 128 + tid];
        atomicAdd(&sum2[ot + tid], s);
    }
    __syncthreads();
#pragma unroll
    for (int j = 0; j < 4; j++) red[rg * 128 + ct * 4 + j] = css[j];
    __syncthreads();
    if (tid < 128) {
        float s = 0.f;
#pragma unroll
        for (int r = 0; r < 8; r++) s += red[r * 128 + tid];
        atomicAdd(&sq2[ot + tid], s);
    }
}

// ---------------------------------------------------------------------------
// Final: apply BN2+ReLU to max/min-selected preact, transposed write (b,o,n)
__global__ void k_final(const float* __restrict__ scale, const float* __restrict__ shift,
                        float* __restrict__ out) {
    __shared__ float t[32][33];
    int b = blockIdx.z;
    int nt = blockIdx.y * 32, otb = blockIdx.x * 32;
    int n = nt + threadIdx.y, o = otb + threadIdx.x;
    int p = b * 1024 + n;
    float s = scale[o];
    float v = (s >= 0.f) ? d_ymax[p * 1024 + o] : d_ymin[p * 1024 + o];
    t[threadIdx.y][threadIdx.x] = fmaxf(fmaf(v, s, shift[o]), 0.f);
    __syncthreads();
    out[b * 1048576 + (otb + threadIdx.y) * 1024 + nt + threadIdx.x] =
        t[threadIdx.x][threadIdx.y];
}

// ---------------------------------------------------------------------------
extern "C" void kernel_launch(void* const* d_in, const int* in_sizes, int n_in,
                              void* d_out, int out_size) {
    const float* xyz = (const float*)d_in[0];
    const float* W1  = (const float*)d_in[1];
    const float* g1  = (const float*)d_in[2];
    const float* b1  = (const float*)d_in[3];
    const float* W2  = (const float*)d_in[4];
    const float* g2  = (const float*)d_in[5];
    const float* b2  = (const float*)d_in[6];
    const float* WA1 = (const float*)d_in[7];
    const float* gA1 = (const float*)d_in[8];
    const float* bA1 = (const float*)d_in[9];
    const float* WA2 = (const float*)d_in[10];
    const float* gA2 = (const float*)d_in[11];
    const float* bA2 = (const float*)d_in[12];
    const float* WB1 = (const float*)d_in[13];
    const float* gB1 = (const float*)d_in[14];
    const float* bB1 = (const float*)d_in[15];
    const float* WB2 = (const float*)d_in[16];
    const float* gB2 = (const float*)d_in[17];
    const float* bB2 = (const float*)d_in[18];
    float* out = (float*)d_out;

    float *h1, *h2, *G, *C, *lA, *sum, *sq, *scale, *shift;
    cudaGetSymbolAddress((void**)&h1, d_h1);
    cudaGetSymbolAddress((void**)&h2, d_h2);
    cudaGetSymbolAddress((void**)&G, d_G);
    cudaGetSymbolAddress((void**)&C, d_C);
    cudaGetSymbolAddress((void**)&lA, d_lA);
    cudaGetSymbolAddress((void**)&sum, d_sum);
    cudaGetSymbolAddress((void**)&sq, d_sq);
    cudaGetSymbolAddress((void**)&scale, d_scale);
    cudaGetSymbolAddress((void**)&shift, d_shift);

    k_zero<<<24, 256>>>(sum, 6 * 1024);
    k_zero<<<24, 256>>>(sq, 6 * 1024);
    k_knn<<<32, 256>>>(xyz);

    // stage 0
    k_gemm<<<dim3(1, 128), 256>>>(xyz, 3, W1, 3, 0, 0, h1, NPTS, 64, 3, sum, sq);
    k_finalize<<<1, 256>>>(sum, sq, g1, b1, scale, shift, 64, 1.f / NPTS);
    k_apply<<<NPTS * 64 / 256, 256>>>(h1, scale, shift, NPTS * 64, 63);
    k_gemm<<<dim3(4, 128), 256>>>(h1, 64, W2, 64, 0, 0, h2, NPTS, 256, 64,
                                  sum + 1024, sq + 1024);
    k_finalize<<<1, 256>>>(sum + 1024, sq + 1024, g2, b2, scale + 1024, shift + 1024,
                           256, 1.f / NPTS);
    k_apply<<<NPTS * 256 / 256, 256>>>(h2, scale + 1024, shift + 1024, NPTS * 256, 255);

    // stage A: G = h2 @ Wl^T, C = h2 @ (Wr-Wl)^T
    k_gemm<<<dim3(8, 128), 256>>>(h2, 256, WA1, 512, 0, 0, G, NPTS, 512, 256, 0, 0);
    k_gemm<<<dim3(8, 128), 256>>>(h2, 256, WA1, 512, 256, 1, C, NPTS, 512, 256, 0, 0);
    k_stats1<512><<<dim3(4, NPTS / 8), 128>>>(sum + 2048, sq + 2048);
    k_finalize<<<2, 256>>>(sum + 2048, sq + 2048, gA1, bA1, scale + 2048, shift + 2048,
                           512, 1.f / 65536.f);
    k_layer2<512><<<dim3(4, NPTS / 8), 256>>>(WA2, scale + 2048, shift + 2048,
                                              sum + 3072, sq + 3072);
    k_finalize<<<2, 256>>>(sum + 3072, sq + 3072, gA2, bA2, scale + 3072, shift + 3072,
                           512, 1.f / 65536.f);
    {
        float *ymx, *ymn;
        cudaGetSymbolAddress((void**)&ymx, d_ymax);
        cudaGetSymbolAddress((void**)&ymn, d_ymin);
        k_apply_sel<<<NPTS * 512 / 256, 256>>>(ymx, ymn, scale + 3072, shift + 3072,
                                               lA, NPTS * 512, 511);
    }

    // stage B
    k_gemm<<<dim3(16, 128), 256>>>(lA, 512, WB1, 1024, 0, 0, G, NPTS, 1024, 512, 0, 0);
    k_gemm<<<dim3(16, 128), 256>>>(lA, 512, WB1, 1024, 512, 1, C, NPTS, 1024, 512, 0, 0);
    k_stats1<1024><<<dim3(8, NPTS / 8), 128>>>(sum + 4096, sq + 4096);
    k_finalize<<<4, 256>>>(sum + 4096, sq + 4096, gB1, bB1, scale + 4096, shift + 4096,
                           1024, 1.f / 65536.f);
    k_layer2<1024><<<dim3(8, NPTS / 8), 256>>>(WB2, scale + 4096, shift + 4096,
                                               sum + 5120, sq + 5120);
    k_finalize<<<4, 256>>>(sum + 5120, sq + 5120, gB2, bB2, scale + 5120, shift + 5120,
                           1024, 1.f / 65536.f);
    k_final<<<dim3(32, 32, 8), dim3(32, 32)>>>(scale + 5120, shift + 5120, out);
}